// round 8
// baseline (speedup 1.0000x reference)
#include <cuda_runtime.h>
#include <cuda_fp16.h>

#define NN   100000
#define NE   1250000
#define FEATD 64
#define HIDD  10
#define PADD  12          // fp32 agg rows: 12 floats (48B, 16B-aligned)
#define HROW  16          // fp16 A rows: 16 halves (32B)
#define INV_MOD 0.1f
#define FULLM 0xffffffffu

// Scratch (no cudaMalloc allowed).
__device__ __half g_Ah[NN * HROW];   // per-node dst-side projection (fp16, 32B rows)
__device__ uint4  g_Bq[NN];          // per-node src-side projection (10x12bit + exp, 16B rows)
__device__ float  g_agg[NN * PADD];  // per-node aggregation buffer (fp32)
__device__ int    g_cnt[NN];         // histogram -> scatter cursor
__device__ int2   g_edge[NE];        // (src, dst) sorted by dst

__device__ __forceinline__ void fma4(float4& acc, float s, const float4 w) {
    acc.x = fmaf(s, w.x, acc.x);
    acc.y = fmaf(s, w.y, acc.y);
    acc.z = fmaf(s, w.z, acc.z);
    acc.w = fmaf(s, w.w, acc.w);
}

// Pack 10 fp32 (3 float4s, lanes 10/11 pad) into a 32B fp16 row.
__device__ __forceinline__ void store_half_row(__half* row, const float4 v0,
                                               const float4 v1, const float4 v2) {
    __align__(16) __half2 h[8];
    h[0] = __floats2half2_rn(v0.x, v0.y);
    h[1] = __floats2half2_rn(v0.z, v0.w);
    h[2] = __floats2half2_rn(v1.x, v1.y);
    h[3] = __floats2half2_rn(v1.z, v1.w);
    h[4] = __floats2half2_rn(v2.x, v2.y);
    h[5] = __floats2half2_rn(0.f, 0.f);
    h[6] = h[5]; h[7] = h[5];
    uint4* p = (uint4*)row;
    p[0] = *(const uint4*)&h[0];
    p[1] = *(const uint4*)&h[4];
}

// Pack 10 fp32 into 16B: 10 x 12-bit biased fixed-point + shared exponent byte.
// step = 2^(eb-11); value_i ~= (q_i - 2048) * step, |err| <= step/2 = rowmax/4096.
__device__ __forceinline__ void store_q_row(uint4* dst, const float* b) {
    float m = 0.f;
    #pragma unroll
    for (int i = 0; i < 10; i++) m = fmaxf(m, fabsf(b[i]));
    int eb = 0;
    frexpf(m, &eb);                       // m in [0.5,1)*2^eb; m==0 -> eb=0
    int ebc = min(max(116 + eb, 1), 254); // exponent byte for step = 2^(eb-11)
    float invstep = __uint_as_float((unsigned)(254 - ebc) << 23);  // 2^(11-eb)
    unsigned wds[4] = {0u, 0u, 0u, 0u};
    #pragma unroll
    for (int i = 0; i < 10; i++) {
        int q = __float2int_rn(b[i] * invstep);
        q = min(max(q, -2047), 2047);
        unsigned uq = (unsigned)(q + 2048);
        int off = 12 * i, wi = off >> 5, sh = off & 31;
        wds[wi] |= uq << sh;
        if (sh > 20) wds[wi + 1] |= uq >> (32 - sh);
    }
    wds[3] |= (unsigned)ebc << 24;
    *dst = make_uint4(wds[0], wds[1], wds[2], wds[3]);
}

// ======================= sort helper kernels ================================

__global__ void __launch_bounds__(256) k_hist(const int* __restrict__ ed) {
    int e = blockIdx.x * blockDim.x + threadIdx.x;
    if (e < NE) atomicAdd(&g_cnt[ed[e]], 1);
}

// One-block exclusive scan over g_cnt[NN] (counts -> segment start cursors).
#define SCTH 1024
#define SCCH ((NN + SCTH - 1) / SCTH)   // 98 elements per thread
__global__ void __launch_bounds__(SCTH) k_scan_all() {
    __shared__ int s[SCTH];
    int tid = threadIdx.x;
    int base = tid * SCCH;

    int sum = 0;
    for (int i = 0; i < SCCH; i++) {
        int idx = base + i;
        if (idx < NN) sum += g_cnt[idx];
    }
    int v = sum;
    s[tid] = v;
    __syncthreads();
    #pragma unroll
    for (int st = 1; st < SCTH; st <<= 1) {
        int t = (tid >= st) ? s[tid - st] : 0;
        __syncthreads();
        s[tid] += t;
        __syncthreads();
    }
    int run = s[tid] - v;   // exclusive prefix of this thread's chunk
    for (int i = 0; i < SCCH; i++) {
        int idx = base + i;
        if (idx < NN) {
            int c = g_cnt[idx];
            g_cnt[idx] = run;
            run += c;
        }
    }
}

__global__ void __launch_bounds__(256) k_scatter(const int* __restrict__ es,
                                                 const int* __restrict__ ed) {
    int e = blockIdx.x * blockDim.x + threadIdx.x;
    if (e >= NE) return;
    int d = ed[e];
    int pos = atomicAdd(&g_cnt[d], 1);
    g_edge[pos] = make_int2(es[e], d);
}

// ========================= node precompute kernels ==========================

__global__ void __launch_bounds__(128) pre0(const float* __restrict__ X,
                                            const float* __restrict__ W2) {
    __shared__ float sW[128 * PADD];      // [128,10] padded to [128,12]
    for (int i = threadIdx.x; i < 128 * PADD; i += blockDim.x) {
        int f = i / PADD, k = i % PADD;
        sW[i] = (k < HIDD) ? W2[f * HIDD + k] : 0.0f;
    }
    __syncthreads();

    int n = blockIdx.x * blockDim.x + threadIdx.x;
    if (n >= NN) return;

    g_cnt[n] = 0;                         // zero the histogram (pre0 runs first)

    const float4* xr  = (const float4*)(X + (long)n * FEATD);
    const float4* sW4 = (const float4*)sW;

    float4 a[3], b[3];
    #pragma unroll
    for (int c = 0; c < 3; c++) { a[c] = make_float4(0.f,0.f,0.f,0.f); b[c] = make_float4(0.f,0.f,0.f,0.f); }

    #pragma unroll 4
    for (int f4 = 0; f4 < 16; f4++) {
        float4 x = xr[f4];
        float xs[4] = {x.x, x.y, x.z, x.w};
        #pragma unroll
        for (int q = 0; q < 4; q++) {
            int f = f4 * 4 + q;
            #pragma unroll
            for (int c = 0; c < 3; c++) {
                fma4(a[c], xs[q], sW4[f * 3 + c]);
                fma4(b[c], xs[q], sW4[(FEATD + f) * 3 + c]);
            }
        }
    }

    store_half_row(g_Ah + (size_t)n * HROW, a[0], a[1], a[2]);
    float bb[10] = {b[0].x, b[0].y, b[0].z, b[0].w,
                    b[1].x, b[1].y, b[1].z, b[1].w,
                    b[2].x, b[2].y};
    store_q_row(&g_Bq[n], bb);

    float4* Gr = (float4*)(g_agg + (long)n * PADD);
    float4 z = make_float4(0.f, 0.f, 0.f, 0.f);
    Gr[0] = z; Gr[1] = z; Gr[2] = z;
}

__global__ void __launch_bounds__(128) pre12(const float* __restrict__ W2) {
    __shared__ float sW[20 * PADD];
    for (int i = threadIdx.x; i < 20 * PADD; i += blockDim.x) {
        int r = i / PADD, k = i % PADD;
        sW[i] = (k < HIDD) ? W2[r * HIDD + k] : 0.0f;
    }
    __syncthreads();

    int n = blockIdx.x * blockDim.x + threadIdx.x;
    if (n >= NN) return;

    float4* Gr = (float4*)(g_agg + (long)n * PADD);
    float4 g0 = Gr[0], g1 = Gr[1], g2 = Gr[2];
    float h[HIDD];
    h[0]=fmaxf(g0.x,0.f); h[1]=fmaxf(g0.y,0.f); h[2]=fmaxf(g0.z,0.f); h[3]=fmaxf(g0.w,0.f);
    h[4]=fmaxf(g1.x,0.f); h[5]=fmaxf(g1.y,0.f); h[6]=fmaxf(g1.z,0.f); h[7]=fmaxf(g1.w,0.f);
    h[8]=fmaxf(g2.x,0.f); h[9]=fmaxf(g2.y,0.f);

    const float4* sW4 = (const float4*)sW;
    float4 a[3], b[3];
    #pragma unroll
    for (int c = 0; c < 3; c++) { a[c] = make_float4(0.f,0.f,0.f,0.f); b[c] = make_float4(0.f,0.f,0.f,0.f); }
    #pragma unroll
    for (int k = 0; k < HIDD; k++) {
        #pragma unroll
        for (int c = 0; c < 3; c++) {
            fma4(a[c], h[k], sW4[k * 3 + c]);
            fma4(b[c], h[k], sW4[(HIDD + k) * 3 + c]);
        }
    }

    store_half_row(g_Ah + (size_t)n * HROW, a[0], a[1], a[2]);
    float bb[10] = {b[0].x, b[0].y, b[0].z, b[0].w,
                    b[1].x, b[1].y, b[1].z, b[1].w,
                    b[2].x, b[2].y};
    store_q_row(&g_Bq[n], bb);

    float4 z = make_float4(0.f, 0.f, 0.f, 0.f);
    Gr[0] = z; Gr[1] = z; Gr[2] = z;
}

// =============================== edge kernel ================================
// Edges sorted by dst. B row = ONE scattered LDG.128 (12-bit packed);
// A row coalesced (sorted dst); warp-segmented shfl reduce; heads issue REDs.

union H8 { uint4 u; __half2 h[4]; };
union H2 { unsigned u; __half2 h; };

__global__ void __launch_bounds__(256) edge_kernel(const float* __restrict__ W1) {
    __shared__ float sW[HIDD * PADD];     // [10,10] padded to [10,12]
    for (int i = threadIdx.x; i < HIDD * PADD; i += blockDim.x) {
        int k = i / PADD, j = i % PADD;
        sW[i] = (j < HIDD) ? W1[k * HIDD + j] : 0.0f;
    }
    __syncthreads();

    int e = blockIdx.x * blockDim.x + threadIdx.x;
    int lane = threadIdx.x & 31;

    int s = 0, d = -1;
    if (e < NE) { int2 sd = g_edge[e]; s = sd.x; d = sd.y; }

    float u[10];
    #pragma unroll
    for (int i = 0; i < 10; i++) u[i] = 0.f;

    if (d >= 0) {
        // A: fp16 32B row, dst-sorted -> broadcast-coalesced.
        const __half* rowA = g_Ah + (size_t)d * HROW;
        H8 aL; H2 aH;
        aL.u = *(const uint4*)rowA;
        aH.u = *(const unsigned*)(rowA + 8);
        float2 fa0 = __half22float2(aL.h[0]);
        float2 fa1 = __half22float2(aL.h[1]);
        float2 fa2 = __half22float2(aL.h[2]);
        float2 fa3 = __half22float2(aL.h[3]);
        float2 fa4 = __half22float2(aH.h);
        float av[10] = {fa0.x, fa0.y, fa1.x, fa1.y, fa2.x,
                        fa2.y, fa3.x, fa3.y, fa4.x, fa4.y};

        // B: single scattered 16B load, 12-bit shared-exponent decode.
        uint4 bq = __ldg(&g_Bq[s]);
        float step = __uint_as_float((bq.w >> 24) << 23);
        float bias = -2048.0f * step;
        unsigned wds[4] = {bq.x, bq.y, bq.z, bq.w};

        float t[HIDD];
        #pragma unroll
        for (int i = 0; i < 10; i++) {
            int off = 12 * i, wi = off >> 5, sh = off & 31;
            unsigned hi = (wi < 3) ? wds[wi + 1] : wds[0];  // hi unused when no straddle
            unsigned uq = __funnelshift_r(wds[wi], hi, sh) & 0xFFFu;
            float bv = fmaf((float)uq, step, bias);
            t[i] = fmaxf(av[i] + bv, 0.f);
        }

        const float4* sW4 = (const float4*)sW;
        float4 u0 = make_float4(0.f,0.f,0.f,0.f);
        float4 u1 = make_float4(0.f,0.f,0.f,0.f);
        float4 u2 = make_float4(0.f,0.f,0.f,0.f);
        #pragma unroll
        for (int k = 0; k < HIDD; k++) {
            float tk = t[k];
            fma4(u0, tk, sW4[k * 3 + 0]);
            fma4(u1, tk, sW4[k * 3 + 1]);
            fma4(u2, tk, sW4[k * 3 + 2]);
        }

        u[0]=fmaxf(u0.x,0.f)*INV_MOD; u[1]=fmaxf(u0.y,0.f)*INV_MOD;
        u[2]=fmaxf(u0.z,0.f)*INV_MOD; u[3]=fmaxf(u0.w,0.f)*INV_MOD;
        u[4]=fmaxf(u1.x,0.f)*INV_MOD; u[5]=fmaxf(u1.y,0.f)*INV_MOD;
        u[6]=fmaxf(u1.z,0.f)*INV_MOD; u[7]=fmaxf(u1.w,0.f)*INV_MOD;
        u[8]=fmaxf(u2.x,0.f)*INV_MOD; u[9]=fmaxf(u2.y,0.f)*INV_MOD;
    }

    // Warp-segmented suffix reduction over same-dst runs (sorted -> contiguous).
    #pragma unroll
    for (int off = 1; off < 32; off <<= 1) {
        int od = __shfl_down_sync(FULLM, d, off);
        float ov[10];
        #pragma unroll
        for (int i = 0; i < 10; i++) ov[i] = __shfl_down_sync(FULLM, u[i], off);
        bool take = (lane + off < 32) && (od == d);
        #pragma unroll
        for (int i = 0; i < 10; i++) if (take) u[i] += ov[i];
    }

    int pd = __shfl_up_sync(FULLM, d, 1);
    bool head = (lane == 0) || (pd != d);

    if (head && d >= 0) {
        float* Gr = g_agg + (long)d * PADD;   // 48B rows -> base 16B-aligned
        asm volatile("red.global.add.v4.f32 [%0], {%1, %2, %3, %4};"
                     :: "l"(Gr), "f"(u[0]), "f"(u[1]), "f"(u[2]), "f"(u[3]) : "memory");
        asm volatile("red.global.add.v4.f32 [%0], {%1, %2, %3, %4};"
                     :: "l"(Gr + 4), "f"(u[4]), "f"(u[5]), "f"(u[6]), "f"(u[7]) : "memory");
        asm volatile("red.global.add.v2.f32 [%0], {%1, %2};"
                     :: "l"(Gr + 8), "f"(u[8]), "f"(u[9]) : "memory");
    }
}

// ============================ fused final head ==============================

__global__ void __launch_bounds__(128) final_fused(const float* __restrict__ Wf1,
                                                   const float* __restrict__ Wf2,
                                                   float* __restrict__ out) {
    __shared__ float sW1[HIDD * FEATD];   // 2.5 KB
    __shared__ float sW2[FEATD * FEATD];  // 16 KB
    for (int i = threadIdx.x; i < HIDD * FEATD; i += blockDim.x) sW1[i] = Wf1[i];
    for (int i = threadIdx.x; i < FEATD * FEATD; i += blockDim.x) sW2[i] = Wf2[i];
    __syncthreads();

    int n = blockIdx.x * blockDim.x + threadIdx.x;
    if (n >= NN) return;

    const float4* Gr = (const float4*)(g_agg + (long)n * PADD);
    float4 g0 = Gr[0], g1 = Gr[1], g2 = Gr[2];
    float h[HIDD];
    h[0]=fmaxf(g0.x,0.f); h[1]=fmaxf(g0.y,0.f); h[2]=fmaxf(g0.z,0.f); h[3]=fmaxf(g0.w,0.f);
    h[4]=fmaxf(g1.x,0.f); h[5]=fmaxf(g1.y,0.f); h[6]=fmaxf(g1.z,0.f); h[7]=fmaxf(g1.w,0.f);
    h[8]=fmaxf(g2.x,0.f); h[9]=fmaxf(g2.y,0.f);

    const float4* sW1_4 = (const float4*)sW1;
    float4 t[16];
    #pragma unroll
    for (int c = 0; c < 16; c++) t[c] = make_float4(0.f,0.f,0.f,0.f);
    #pragma unroll
    for (int k = 0; k < HIDD; k++) {
        float hk = h[k];
        #pragma unroll
        for (int c = 0; c < 16; c++) fma4(t[c], hk, sW1_4[k * 16 + c]);
    }
    #pragma unroll
    for (int c = 0; c < 16; c++) {
        t[c].x = fmaxf(t[c].x, 0.f); t[c].y = fmaxf(t[c].y, 0.f);
        t[c].z = fmaxf(t[c].z, 0.f); t[c].w = fmaxf(t[c].w, 0.f);
    }

    const float4* sW2_4 = (const float4*)sW2;
    float4 acc[16];
    #pragma unroll
    for (int c = 0; c < 16; c++) acc[c] = make_float4(0.f,0.f,0.f,0.f);

    for (int g4 = 0; g4 < 16; g4++) {
        float4 x = t[g4];
        float xs[4] = {x.x, x.y, x.z, x.w};
        #pragma unroll
        for (int q = 0; q < 4; q++) {
            int g = g4 * 4 + q;
            float xg = xs[q];
            #pragma unroll
            for (int c = 0; c < 16; c++) fma4(acc[c], xg, sW2_4[g * 16 + c]);
        }
    }

    float4* orow = (float4*)(out + (long)n * FEATD);
    #pragma unroll
    for (int c = 0; c < 16; c++) {
        float4 v = acc[c];
        v.x = fmaxf(v.x, 0.f); v.y = fmaxf(v.y, 0.f);
        v.z = fmaxf(v.z, 0.f); v.w = fmaxf(v.w, 0.f);
        orow[c] = v;
    }
}

// ---------------------------------------------------------------------------
// Inputs (metadata order): X, W2_0, W1_0, W2_1, W1_1, W2_2, W1_2, Wf1, Wf2,
//                          edge_src (int32), edge_dst (int32)
// ---------------------------------------------------------------------------
extern "C" void kernel_launch(void* const* d_in, const int* in_sizes, int n_in,
                              void* d_out, int out_size) {
    const float* X    = (const float*)d_in[0];
    const float* W2_0 = (const float*)d_in[1];
    const float* W1_0 = (const float*)d_in[2];
    const float* W2_1 = (const float*)d_in[3];
    const float* W1_1 = (const float*)d_in[4];
    const float* W2_2 = (const float*)d_in[5];
    const float* W1_2 = (const float*)d_in[6];
    const float* Wf1  = (const float*)d_in[7];
    const float* Wf2  = (const float*)d_in[8];
    const int*   es   = (const int*)d_in[9];
    const int*   ed   = (const int*)d_in[10];
    float* out = (float*)d_out;

    const int nodeBlocks = (NN + 127) / 128;
    const int edgeBlocks = (NE + 255) / 256;

    // pre0 runs first: computes layer-0 A/B, zeroes agg AND g_cnt.
    pre0<<<nodeBlocks, 128>>>(X, W2_0);
    // Build dst-sorted edge list (counting sort), reused by all 3 layers.
    k_hist<<<edgeBlocks, 256>>>(ed);
    k_scan_all<<<1, SCTH>>>();
    k_scatter<<<edgeBlocks, 256>>>(es, ed);

    edge_kernel<<<edgeBlocks, 256>>>(W1_0);
    pre12<<<nodeBlocks, 128>>>(W2_1);
    edge_kernel<<<edgeBlocks, 256>>>(W1_1);
    pre12<<<nodeBlocks, 128>>>(W2_2);
    edge_kernel<<<edgeBlocks, 256>>>(W1_2);
    final_fused<<<nodeBlocks, 128>>>(Wf1, Wf2, out);
}

// round 9
// speedup vs baseline: 1.6682x; 1.6682x over previous
#include <cuda_runtime.h>
#include <cuda_fp16.h>

#define NN   100000
#define NE   1250000
#define FEATD 64
#define HIDD  10
#define PADD  12          // fp32 agg rows: 12 floats (48B, 16B-aligned)
#define HROW  16          // fp16 A rows: 16 halves (32B)
#define INV_MOD 0.1f
#define FULLM 0xffffffffu

#define SCB  512                       // scan block size
#define NSB  ((NN + SCB - 1) / SCB)    // 196 scan blocks

// Scratch (no cudaMalloc allowed).
__device__ __half g_Ah[NN * HROW];   // per-node dst-side projection (fp16, 32B rows)
__device__ uint4  g_Bq[NN];          // per-node src-side projection (10x12bit + exp, 16B)
__device__ float  g_agg[NN * PADD];  // per-node aggregation buffer (fp32)
__device__ int    g_cnt[NN];         // histogram -> scatter cursor
__device__ int    g_bsum[NSB];       // scan block partials
__device__ int2   g_edge[NE];        // (src, dst) sorted by dst

__device__ __forceinline__ void fma4(float4& acc, float s, const float4 w) {
    acc.x = fmaf(s, w.x, acc.x);
    acc.y = fmaf(s, w.y, acc.y);
    acc.z = fmaf(s, w.z, acc.z);
    acc.w = fmaf(s, w.w, acc.w);
}

// Pack 10 fp32 (3 float4s, lanes 10/11 pad) into a 32B fp16 row.
__device__ __forceinline__ void store_half_row(__half* row, const float4 v0,
                                               const float4 v1, const float4 v2) {
    __align__(16) __half2 h[8];
    h[0] = __floats2half2_rn(v0.x, v0.y);
    h[1] = __floats2half2_rn(v0.z, v0.w);
    h[2] = __floats2half2_rn(v1.x, v1.y);
    h[3] = __floats2half2_rn(v1.z, v1.w);
    h[4] = __floats2half2_rn(v2.x, v2.y);
    h[5] = __floats2half2_rn(0.f, 0.f);
    h[6] = h[5]; h[7] = h[5];
    uint4* p = (uint4*)row;
    p[0] = *(const uint4*)&h[0];
    p[1] = *(const uint4*)&h[4];
}

// Pack 10 fp32 into 16B: 10 x 12-bit biased fixed-point + shared exponent byte.
// step = 2^(eb-11); value_i ~= (q_i - 2048) * step, |err| <= step/2 = rowmax/4096.
__device__ __forceinline__ void store_q_row(uint4* dst, const float* b) {
    float m = 0.f;
    #pragma unroll
    for (int i = 0; i < 10; i++) m = fmaxf(m, fabsf(b[i]));
    int eb = 0;
    frexpf(m, &eb);                       // m in [0.5,1)*2^eb; m==0 -> eb=0
    int ebc = min(max(116 + eb, 1), 254); // exponent byte for step = 2^(eb-11)
    float invstep = __uint_as_float((unsigned)(254 - ebc) << 23);  // 2^(11-eb)
    unsigned wds[4] = {0u, 0u, 0u, 0u};
    #pragma unroll
    for (int i = 0; i < 10; i++) {
        int q = __float2int_rn(b[i] * invstep);
        q = min(max(q, -2047), 2047);
        unsigned uq = (unsigned)(q + 2048);
        int off = 12 * i, wi = off >> 5, sh = off & 31;
        wds[wi] |= uq << sh;
        if (sh > 20) wds[wi + 1] |= uq >> (32 - sh);
    }
    wds[3] |= (unsigned)ebc << 24;
    *dst = make_uint4(wds[0], wds[1], wds[2], wds[3]);
}

// ======================= sort helper kernels ================================

__global__ void __launch_bounds__(256) k_hist(const int* __restrict__ ed) {
    int e = blockIdx.x * blockDim.x + threadIdx.x;
    if (e < NE) atomicAdd(&g_cnt[ed[e]], 1);
}

// Per-block reduction of counts -> g_bsum[b]. (coalesced, 196 blocks)
__global__ void __launch_bounds__(SCB) k_scan1() {
    __shared__ int s[SCB];
    int i = blockIdx.x * SCB + threadIdx.x;
    s[threadIdx.x] = (i < NN) ? g_cnt[i] : 0;
    __syncthreads();
    for (int st = SCB / 2; st > 0; st >>= 1) {
        if (threadIdx.x < st) s[threadIdx.x] += s[threadIdx.x + st];
        __syncthreads();
    }
    if (threadIdx.x == 0) g_bsum[blockIdx.x] = s[0];
}

// Parallel exclusive scan over NSB block sums (one 256-thread block).
__global__ void __launch_bounds__(256) k_scan2() {
    __shared__ int s[256];
    int i = threadIdx.x;
    int v = (i < NSB) ? g_bsum[i] : 0;
    s[i] = v;
    __syncthreads();
    #pragma unroll
    for (int st = 1; st < 256; st <<= 1) {
        int t = (i >= st) ? s[i - st] : 0;
        __syncthreads();
        s[i] += t;
        __syncthreads();
    }
    if (i < NSB) g_bsum[i] = s[i] - v;   // exclusive
}

// Exclusive scan within block + block base -> g_cnt becomes segment-start cursor.
__global__ void __launch_bounds__(SCB) k_scan3() {
    __shared__ int s[SCB];
    int i = blockIdx.x * SCB + threadIdx.x;
    int v = (i < NN) ? g_cnt[i] : 0;
    s[threadIdx.x] = v;
    __syncthreads();
    #pragma unroll
    for (int st = 1; st < SCB; st <<= 1) {
        int t = (threadIdx.x >= st) ? s[threadIdx.x - st] : 0;
        __syncthreads();
        s[threadIdx.x] += t;
        __syncthreads();
    }
    if (i < NN) g_cnt[i] = g_bsum[blockIdx.x] + (s[threadIdx.x] - v);
}

__global__ void __launch_bounds__(256) k_scatter(const int* __restrict__ es,
                                                 const int* __restrict__ ed) {
    int e = blockIdx.x * blockDim.x + threadIdx.x;
    if (e >= NE) return;
    int d = ed[e];
    int pos = atomicAdd(&g_cnt[d], 1);
    g_edge[pos] = make_int2(es[e], d);
}

// ========================= node precompute kernels ==========================

__global__ void __launch_bounds__(128) pre0(const float* __restrict__ X,
                                            const float* __restrict__ W2) {
    __shared__ float sW[128 * PADD];      // [128,10] padded to [128,12]
    for (int i = threadIdx.x; i < 128 * PADD; i += blockDim.x) {
        int f = i / PADD, k = i % PADD;
        sW[i] = (k < HIDD) ? W2[f * HIDD + k] : 0.0f;
    }
    __syncthreads();

    int n = blockIdx.x * blockDim.x + threadIdx.x;
    if (n >= NN) return;

    g_cnt[n] = 0;                         // zero the histogram (pre0 runs first)

    const float4* xr  = (const float4*)(X + (long)n * FEATD);
    const float4* sW4 = (const float4*)sW;

    float4 a[3], b[3];
    #pragma unroll
    for (int c = 0; c < 3; c++) { a[c] = make_float4(0.f,0.f,0.f,0.f); b[c] = make_float4(0.f,0.f,0.f,0.f); }

    #pragma unroll 4
    for (int f4 = 0; f4 < 16; f4++) {
        float4 x = xr[f4];
        float xs[4] = {x.x, x.y, x.z, x.w};
        #pragma unroll
        for (int q = 0; q < 4; q++) {
            int f = f4 * 4 + q;
            #pragma unroll
            for (int c = 0; c < 3; c++) {
                fma4(a[c], xs[q], sW4[f * 3 + c]);
                fma4(b[c], xs[q], sW4[(FEATD + f) * 3 + c]);
            }
        }
    }

    store_half_row(g_Ah + (size_t)n * HROW, a[0], a[1], a[2]);
    float bb[10] = {b[0].x, b[0].y, b[0].z, b[0].w,
                    b[1].x, b[1].y, b[1].z, b[1].w,
                    b[2].x, b[2].y};
    store_q_row(&g_Bq[n], bb);

    float4* Gr = (float4*)(g_agg + (long)n * PADD);
    float4 z = make_float4(0.f, 0.f, 0.f, 0.f);
    Gr[0] = z; Gr[1] = z; Gr[2] = z;
}

__global__ void __launch_bounds__(128) pre12(const float* __restrict__ W2) {
    __shared__ float sW[20 * PADD];
    for (int i = threadIdx.x; i < 20 * PADD; i += blockDim.x) {
        int r = i / PADD, k = i % PADD;
        sW[i] = (k < HIDD) ? W2[r * HIDD + k] : 0.0f;
    }
    __syncthreads();

    int n = blockIdx.x * blockDim.x + threadIdx.x;
    if (n >= NN) return;

    float4* Gr = (float4*)(g_agg + (long)n * PADD);
    float4 g0 = Gr[0], g1 = Gr[1], g2 = Gr[2];
    float h[HIDD];
    h[0]=fmaxf(g0.x,0.f); h[1]=fmaxf(g0.y,0.f); h[2]=fmaxf(g0.z,0.f); h[3]=fmaxf(g0.w,0.f);
    h[4]=fmaxf(g1.x,0.f); h[5]=fmaxf(g1.y,0.f); h[6]=fmaxf(g1.z,0.f); h[7]=fmaxf(g1.w,0.f);
    h[8]=fmaxf(g2.x,0.f); h[9]=fmaxf(g2.y,0.f);

    const float4* sW4 = (const float4*)sW;
    float4 a[3], b[3];
    #pragma unroll
    for (int c = 0; c < 3; c++) { a[c] = make_float4(0.f,0.f,0.f,0.f); b[c] = make_float4(0.f,0.f,0.f,0.f); }
    #pragma unroll
    for (int k = 0; k < HIDD; k++) {
        #pragma unroll
        for (int c = 0; c < 3; c++) {
            fma4(a[c], h[k], sW4[k * 3 + c]);
            fma4(b[c], h[k], sW4[(HIDD + k) * 3 + c]);
        }
    }

    store_half_row(g_Ah + (size_t)n * HROW, a[0], a[1], a[2]);
    float bb[10] = {b[0].x, b[0].y, b[0].z, b[0].w,
                    b[1].x, b[1].y, b[1].z, b[1].w,
                    b[2].x, b[2].y};
    store_q_row(&g_Bq[n], bb);

    float4 z = make_float4(0.f, 0.f, 0.f, 0.f);
    Gr[0] = z; Gr[1] = z; Gr[2] = z;
}

// =============================== edge kernel ================================
// Edges sorted by dst. B row = ONE scattered LDG.128 (12-bit packed);
// A row coalesced (sorted dst); warp-segmented shfl reduce; heads issue REDs.

union H8 { uint4 u; __half2 h[4]; };
union H2 { unsigned u; __half2 h; };

__global__ void __launch_bounds__(256) edge_kernel(const float* __restrict__ W1) {
    __shared__ float sW[HIDD * PADD];     // [10,10] padded to [10,12]
    for (int i = threadIdx.x; i < HIDD * PADD; i += blockDim.x) {
        int k = i / PADD, j = i % PADD;
        sW[i] = (j < HIDD) ? W1[k * HIDD + j] : 0.0f;
    }
    __syncthreads();

    int e = blockIdx.x * blockDim.x + threadIdx.x;
    int lane = threadIdx.x & 31;

    int s = 0, d = -1;
    if (e < NE) { int2 sd = g_edge[e]; s = sd.x; d = sd.y; }

    float u[10];
    #pragma unroll
    for (int i = 0; i < 10; i++) u[i] = 0.f;

    if (d >= 0) {
        // A: fp16 32B row, dst-sorted -> broadcast-coalesced.
        const __half* rowA = g_Ah + (size_t)d * HROW;
        H8 aL; H2 aH;
        aL.u = *(const uint4*)rowA;
        aH.u = *(const unsigned*)(rowA + 8);
        float2 fa0 = __half22float2(aL.h[0]);
        float2 fa1 = __half22float2(aL.h[1]);
        float2 fa2 = __half22float2(aL.h[2]);
        float2 fa3 = __half22float2(aL.h[3]);
        float2 fa4 = __half22float2(aH.h);
        float av[10] = {fa0.x, fa0.y, fa1.x, fa1.y, fa2.x,
                        fa2.y, fa3.x, fa3.y, fa4.x, fa4.y};

        // B: single scattered 16B load, 12-bit shared-exponent decode.
        uint4 bq = __ldg(&g_Bq[s]);
        float step = __uint_as_float((bq.w >> 24) << 23);
        float bias = -2048.0f * step;
        unsigned wds[4] = {bq.x, bq.y, bq.z, bq.w};

        float t[HIDD];
        #pragma unroll
        for (int i = 0; i < 10; i++) {
            int off = 12 * i, wi = off >> 5, sh = off & 31;
            unsigned hi = (wi < 3) ? wds[wi + 1] : wds[0];  // hi unused when no straddle
            unsigned uq = __funnelshift_r(wds[wi], hi, sh) & 0xFFFu;
            float bv = fmaf((float)uq, step, bias);
            t[i] = fmaxf(av[i] + bv, 0.f);
        }

        const float4* sW4 = (const float4*)sW;
        float4 u0 = make_float4(0.f,0.f,0.f,0.f);
        float4 u1 = make_float4(0.f,0.f,0.f,0.f);
        float4 u2 = make_float4(0.f,0.f,0.f,0.f);
        #pragma unroll
        for (int k = 0; k < HIDD; k++) {
            float tk = t[k];
            fma4(u0, tk, sW4[k * 3 + 0]);
            fma4(u1, tk, sW4[k * 3 + 1]);
            fma4(u2, tk, sW4[k * 3 + 2]);
        }

        u[0]=fmaxf(u0.x,0.f)*INV_MOD; u[1]=fmaxf(u0.y,0.f)*INV_MOD;
        u[2]=fmaxf(u0.z,0.f)*INV_MOD; u[3]=fmaxf(u0.w,0.f)*INV_MOD;
        u[4]=fmaxf(u1.x,0.f)*INV_MOD; u[5]=fmaxf(u1.y,0.f)*INV_MOD;
        u[6]=fmaxf(u1.z,0.f)*INV_MOD; u[7]=fmaxf(u1.w,0.f)*INV_MOD;
        u[8]=fmaxf(u2.x,0.f)*INV_MOD; u[9]=fmaxf(u2.y,0.f)*INV_MOD;
    }

    // Warp-segmented suffix reduction over same-dst runs (sorted -> contiguous).
    #pragma unroll
    for (int off = 1; off < 32; off <<= 1) {
        int od = __shfl_down_sync(FULLM, d, off);
        float ov[10];
        #pragma unroll
        for (int i = 0; i < 10; i++) ov[i] = __shfl_down_sync(FULLM, u[i], off);
        bool take = (lane + off < 32) && (od == d);
        #pragma unroll
        for (int i = 0; i < 10; i++) if (take) u[i] += ov[i];
    }

    int pd = __shfl_up_sync(FULLM, d, 1);
    bool head = (lane == 0) || (pd != d);

    if (head && d >= 0) {
        float* Gr = g_agg + (long)d * PADD;   // 48B rows -> base 16B-aligned
        asm volatile("red.global.add.v4.f32 [%0], {%1, %2, %3, %4};"
                     :: "l"(Gr), "f"(u[0]), "f"(u[1]), "f"(u[2]), "f"(u[3]) : "memory");
        asm volatile("red.global.add.v4.f32 [%0], {%1, %2, %3, %4};"
                     :: "l"(Gr + 4), "f"(u[4]), "f"(u[5]), "f"(u[6]), "f"(u[7]) : "memory");
        asm volatile("red.global.add.v2.f32 [%0], {%1, %2};"
                     :: "l"(Gr + 8), "f"(u[8]), "f"(u[9]) : "memory");
    }
}

// ============================ fused final head ==============================

__global__ void __launch_bounds__(128) final_fused(const float* __restrict__ Wf1,
                                                   const float* __restrict__ Wf2,
                                                   float* __restrict__ out) {
    __shared__ float sW1[HIDD * FEATD];   // 2.5 KB
    __shared__ float sW2[FEATD * FEATD];  // 16 KB
    for (int i = threadIdx.x; i < HIDD * FEATD; i += blockDim.x) sW1[i] = Wf1[i];
    for (int i = threadIdx.x; i < FEATD * FEATD; i += blockDim.x) sW2[i] = Wf2[i];
    __syncthreads();

    int n = blockIdx.x * blockDim.x + threadIdx.x;
    if (n >= NN) return;

    const float4* Gr = (const float4*)(g_agg + (long)n * PADD);
    float4 g0 = Gr[0], g1 = Gr[1], g2 = Gr[2];
    float h[HIDD];
    h[0]=fmaxf(g0.x,0.f); h[1]=fmaxf(g0.y,0.f); h[2]=fmaxf(g0.z,0.f); h[3]=fmaxf(g0.w,0.f);
    h[4]=fmaxf(g1.x,0.f); h[5]=fmaxf(g1.y,0.f); h[6]=fmaxf(g1.z,0.f); h[7]=fmaxf(g1.w,0.f);
    h[8]=fmaxf(g2.x,0.f); h[9]=fmaxf(g2.y,0.f);

    const float4* sW1_4 = (const float4*)sW1;
    float4 t[16];
    #pragma unroll
    for (int c = 0; c < 16; c++) t[c] = make_float4(0.f,0.f,0.f,0.f);
    #pragma unroll
    for (int k = 0; k < HIDD; k++) {
        float hk = h[k];
        #pragma unroll
        for (int c = 0; c < 16; c++) fma4(t[c], hk, sW1_4[k * 16 + c]);
    }
    #pragma unroll
    for (int c = 0; c < 16; c++) {
        t[c].x = fmaxf(t[c].x, 0.f); t[c].y = fmaxf(t[c].y, 0.f);
        t[c].z = fmaxf(t[c].z, 0.f); t[c].w = fmaxf(t[c].w, 0.f);
    }

    const float4* sW2_4 = (const float4*)sW2;
    float4 acc[16];
    #pragma unroll
    for (int c = 0; c < 16; c++) acc[c] = make_float4(0.f,0.f,0.f,0.f);

    for (int g4 = 0; g4 < 16; g4++) {
        float4 x = t[g4];
        float xs[4] = {x.x, x.y, x.z, x.w};
        #pragma unroll
        for (int q = 0; q < 4; q++) {
            int g = g4 * 4 + q;
            float xg = xs[q];
            #pragma unroll
            for (int c = 0; c < 16; c++) fma4(acc[c], xg, sW2_4[g * 16 + c]);
        }
    }

    float4* orow = (float4*)(out + (long)n * FEATD);
    #pragma unroll
    for (int c = 0; c < 16; c++) {
        float4 v = acc[c];
        v.x = fmaxf(v.x, 0.f); v.y = fmaxf(v.y, 0.f);
        v.z = fmaxf(v.z, 0.f); v.w = fmaxf(v.w, 0.f);
        orow[c] = v;
    }
}

// ---------------------------------------------------------------------------
// Inputs (metadata order): X, W2_0, W1_0, W2_1, W1_1, W2_2, W1_2, Wf1, Wf2,
//                          edge_src (int32), edge_dst (int32)
// ---------------------------------------------------------------------------
extern "C" void kernel_launch(void* const* d_in, const int* in_sizes, int n_in,
                              void* d_out, int out_size) {
    const float* X    = (const float*)d_in[0];
    const float* W2_0 = (const float*)d_in[1];
    const float* W1_0 = (const float*)d_in[2];
    const float* W2_1 = (const float*)d_in[3];
    const float* W1_1 = (const float*)d_in[4];
    const float* W2_2 = (const float*)d_in[5];
    const float* W1_2 = (const float*)d_in[6];
    const float* Wf1  = (const float*)d_in[7];
    const float* Wf2  = (const float*)d_in[8];
    const int*   es   = (const int*)d_in[9];
    const int*   ed   = (const int*)d_in[10];
    float* out = (float*)d_out;

    const int nodeBlocks = (NN + 127) / 128;
    const int edgeBlocks = (NE + 255) / 256;

    // pre0 runs first: computes layer-0 A/B, zeroes agg AND g_cnt.
    pre0<<<nodeBlocks, 128>>>(X, W2_0);
    // Build dst-sorted edge list (counting sort), reused by all 3 layers.
    k_hist<<<edgeBlocks, 256>>>(ed);
    k_scan1<<<NSB, SCB>>>();
    k_scan2<<<1, 256>>>();
    k_scan3<<<NSB, SCB>>>();
    k_scatter<<<edgeBlocks, 256>>>(es, ed);

    edge_kernel<<<edgeBlocks, 256>>>(W1_0);
    pre12<<<nodeBlocks, 128>>>(W2_1);
    edge_kernel<<<edgeBlocks, 256>>>(W1_1);
    pre12<<<nodeBlocks, 128>>>(W2_2);
    edge_kernel<<<edgeBlocks, 256>>>(W1_2);
    final_fused<<<nodeBlocks, 128>>>(Wf1, Wf2, out);
}

// round 11
// speedup vs baseline: 1.8756x; 1.1244x over previous
#include <cuda_runtime.h>
#include <cuda_fp16.h>

#define NN   100000
#define NE   1250000
#define FEATD 64
#define HIDD  10
#define PADD  12          // fp32 agg rows: 12 floats (48B, 16B-aligned)
#define INV_MOD 0.1f

// Scratch (no cudaMalloc allowed).
__device__ uint4 g_Aq[NN];           // per-node dst-side projection (10x12bit + exp, 16B)
__device__ uint4 g_Bq[NN];           // per-node src-side projection (10x12bit + exp, 16B)
__device__ float g_agg[NN * PADD];   // per-node aggregation buffer (fp32)

__device__ __forceinline__ void fma4(float4& acc, float s, const float4 w) {
    acc.x = fmaf(s, w.x, acc.x);
    acc.y = fmaf(s, w.y, acc.y);
    acc.z = fmaf(s, w.z, acc.z);
    acc.w = fmaf(s, w.w, acc.w);
}

// Packed fp32x2 FMA (FFMA2) — only reachable via PTX on sm_103a.
__device__ __forceinline__ void ffma2(unsigned long long& acc,
                                      unsigned long long a, unsigned long long b) {
    asm("fma.rn.f32x2 %0, %1, %2, %0;" : "+l"(acc) : "l"(a), "l"(b));
}
__device__ __forceinline__ unsigned long long pack2(float lo, float hi) {
    unsigned long long r;
    asm("mov.b64 %0, {%1, %2};" : "=l"(r) : "f"(lo), "f"(hi));
    return r;
}
__device__ __forceinline__ float2 unpack2(unsigned long long v) {
    float lo, hi;
    asm("mov.b64 {%0, %1}, %2;" : "=f"(lo), "=f"(hi) : "l"(v));
    return make_float2(lo, hi);
}

// Pack 10 fp32 into 16B: 10 x 12-bit biased fixed-point + shared exponent byte.
// step = 2^(eb-11); value_i ~= (q_i - 2048) * step, |err| <= step/2 = rowmax/4096.
__device__ __forceinline__ void store_q_row(uint4* dst, const float* b) {
    float m = 0.f;
    #pragma unroll
    for (int i = 0; i < 10; i++) m = fmaxf(m, fabsf(b[i]));
    int eb = 0;
    frexpf(m, &eb);                       // m in [0.5,1)*2^eb; m==0 -> eb=0
    int ebc = min(max(116 + eb, 1), 254); // exponent byte for step = 2^(eb-11)
    float invstep = __uint_as_float((unsigned)(254 - ebc) << 23);  // 2^(11-eb)
    unsigned wds[4] = {0u, 0u, 0u, 0u};
    #pragma unroll
    for (int i = 0; i < 10; i++) {
        int q = __float2int_rn(b[i] * invstep);
        q = min(max(q, -2047), 2047);
        unsigned uq = (unsigned)(q + 2048);
        int off = 12 * i, wi = off >> 5, sh = off & 31;
        wds[wi] |= uq << sh;
        if (sh > 20) wds[wi + 1] |= uq >> (32 - sh);
    }
    wds[3] |= (unsigned)ebc << 24;
    *dst = make_uint4(wds[0], wds[1], wds[2], wds[3]);
}

// Decode a 16B quantized row into v[10] (v_i = uq_i*step - 2048*step).
__device__ __forceinline__ void decode_q_row(const uint4 q, float* v) {
    float step = __uint_as_float((q.w >> 24) << 23);
    float bias = -2048.0f * step;
    unsigned wds[4] = {q.x, q.y, q.z, q.w};
    #pragma unroll
    for (int i = 0; i < 10; i++) {
        int off = 12 * i, wi = off >> 5, sh = off & 31;
        unsigned hi = (wi < 3) ? wds[wi + 1] : wds[0];   // hi unused when no straddle
        unsigned uq = __funnelshift_r(wds[wi], hi, sh) & 0xFFFu;
        v[i] = fmaf((float)uq, step, bias);
    }
}

// ========================= node precompute kernels ==========================

__global__ void __launch_bounds__(128) pre0(const float* __restrict__ X,
                                            const float* __restrict__ W2) {
    __shared__ float sW[128 * PADD];      // [128,10] padded to [128,12]
    for (int i = threadIdx.x; i < 128 * PADD; i += blockDim.x) {
        int f = i / PADD, k = i % PADD;
        sW[i] = (k < HIDD) ? W2[f * HIDD + k] : 0.0f;
    }
    __syncthreads();

    int n = blockIdx.x * blockDim.x + threadIdx.x;
    if (n >= NN) return;

    const float4* xr  = (const float4*)(X + (long)n * FEATD);
    const float4* sW4 = (const float4*)sW;

    float4 a[3], b[3];
    #pragma unroll
    for (int c = 0; c < 3; c++) { a[c] = make_float4(0.f,0.f,0.f,0.f); b[c] = make_float4(0.f,0.f,0.f,0.f); }

    #pragma unroll 4
    for (int f4 = 0; f4 < 16; f4++) {
        float4 x = xr[f4];
        float xs[4] = {x.x, x.y, x.z, x.w};
        #pragma unroll
        for (int q = 0; q < 4; q++) {
            int f = f4 * 4 + q;
            #pragma unroll
            for (int c = 0; c < 3; c++) {
                fma4(a[c], xs[q], sW4[f * 3 + c]);
                fma4(b[c], xs[q], sW4[(FEATD + f) * 3 + c]);
            }
        }
    }

    float aa[10] = {a[0].x, a[0].y, a[0].z, a[0].w,
                    a[1].x, a[1].y, a[1].z, a[1].w,
                    a[2].x, a[2].y};
    float bb[10] = {b[0].x, b[0].y, b[0].z, b[0].w,
                    b[1].x, b[1].y, b[1].z, b[1].w,
                    b[2].x, b[2].y};
    store_q_row(&g_Aq[n], aa);
    store_q_row(&g_Bq[n], bb);

    float4* Gr = (float4*)(g_agg + (long)n * PADD);
    float4 z = make_float4(0.f, 0.f, 0.f, 0.f);
    Gr[0] = z; Gr[1] = z; Gr[2] = z;
}

__global__ void __launch_bounds__(128) pre12(const float* __restrict__ W2) {
    __shared__ float sW[20 * PADD];
    for (int i = threadIdx.x; i < 20 * PADD; i += blockDim.x) {
        int r = i / PADD, k = i % PADD;
        sW[i] = (k < HIDD) ? W2[r * HIDD + k] : 0.0f;
    }
    __syncthreads();

    int n = blockIdx.x * blockDim.x + threadIdx.x;
    if (n >= NN) return;

    float4* Gr = (float4*)(g_agg + (long)n * PADD);
    float4 g0 = Gr[0], g1 = Gr[1], g2 = Gr[2];
    float h[HIDD];
    h[0]=fmaxf(g0.x,0.f); h[1]=fmaxf(g0.y,0.f); h[2]=fmaxf(g0.z,0.f); h[3]=fmaxf(g0.w,0.f);
    h[4]=fmaxf(g1.x,0.f); h[5]=fmaxf(g1.y,0.f); h[6]=fmaxf(g1.z,0.f); h[7]=fmaxf(g1.w,0.f);
    h[8]=fmaxf(g2.x,0.f); h[9]=fmaxf(g2.y,0.f);

    const float4* sW4 = (const float4*)sW;
    float4 a[3], b[3];
    #pragma unroll
    for (int c = 0; c < 3; c++) { a[c] = make_float4(0.f,0.f,0.f,0.f); b[c] = make_float4(0.f,0.f,0.f,0.f); }
    #pragma unroll
    for (int k = 0; k < HIDD; k++) {
        #pragma unroll
        for (int c = 0; c < 3; c++) {
            fma4(a[c], h[k], sW4[k * 3 + c]);
            fma4(b[c], h[k], sW4[(HIDD + k) * 3 + c]);
        }
    }

    float aa[10] = {a[0].x, a[0].y, a[0].z, a[0].w,
                    a[1].x, a[1].y, a[1].z, a[1].w,
                    a[2].x, a[2].y};
    float bb[10] = {b[0].x, b[0].y, b[0].z, b[0].w,
                    b[1].x, b[1].y, b[1].z, b[1].w,
                    b[2].x, b[2].y};
    store_q_row(&g_Aq[n], aa);
    store_q_row(&g_Bq[n], bb);

    float4 z = make_float4(0.f, 0.f, 0.f, 0.f);
    Gr[0] = z; Gr[1] = z; Gr[2] = z;
}

// =============================== edge kernel ================================
// Unsorted edge-parallel. A and B rows each ONE scattered 16B LDG (12-bit
// packed). t = relu(A[dst]+B[src]); u = relu(t @ W1)/MOD; vector REDs to agg.

__global__ void __launch_bounds__(256) edge_kernel(const int* __restrict__ es,
                                                   const int* __restrict__ ed,
                                                   const float* __restrict__ W1) {
    __shared__ float sW[HIDD * PADD];     // [10,10] padded to [10,12]
    for (int i = threadIdx.x; i < HIDD * PADD; i += blockDim.x) {
        int k = i / PADD, j = i % PADD;
        sW[i] = (j < HIDD) ? W1[k * HIDD + j] : 0.0f;
    }
    __syncthreads();

    int e = blockIdx.x * blockDim.x + threadIdx.x;
    if (e >= NE) return;

    int s = es[e];
    int d = ed[e];

    uint4 aq = __ldg(&g_Aq[d]);
    uint4 bq = __ldg(&g_Bq[s]);

    float av[10], bv[10];
    decode_q_row(aq, av);
    decode_q_row(bq, bv);

    float t[HIDD];
    #pragma unroll
    for (int i = 0; i < 10; i++) t[i] = fmaxf(av[i] + bv[i], 0.f);

    const float4* sW4 = (const float4*)sW;
    float4 u0 = make_float4(0.f,0.f,0.f,0.f);
    float4 u1 = make_float4(0.f,0.f,0.f,0.f);
    float4 u2 = make_float4(0.f,0.f,0.f,0.f);
    #pragma unroll
    for (int k = 0; k < HIDD; k++) {
        float tk = t[k];
        fma4(u0, tk, sW4[k * 3 + 0]);
        fma4(u1, tk, sW4[k * 3 + 1]);
        fma4(u2, tk, sW4[k * 3 + 2]);
    }

    u0.x = fmaxf(u0.x,0.f)*INV_MOD; u0.y = fmaxf(u0.y,0.f)*INV_MOD;
    u0.z = fmaxf(u0.z,0.f)*INV_MOD; u0.w = fmaxf(u0.w,0.f)*INV_MOD;
    u1.x = fmaxf(u1.x,0.f)*INV_MOD; u1.y = fmaxf(u1.y,0.f)*INV_MOD;
    u1.z = fmaxf(u1.z,0.f)*INV_MOD; u1.w = fmaxf(u1.w,0.f)*INV_MOD;
    u2.x = fmaxf(u2.x,0.f)*INV_MOD; u2.y = fmaxf(u2.y,0.f)*INV_MOD;

    float* Gr = g_agg + (long)d * PADD;   // 48B rows -> base 16B-aligned
    asm volatile("red.global.add.v4.f32 [%0], {%1, %2, %3, %4};"
                 :: "l"(Gr), "f"(u0.x), "f"(u0.y), "f"(u0.z), "f"(u0.w) : "memory");
    asm volatile("red.global.add.v4.f32 [%0], {%1, %2, %3, %4};"
                 :: "l"(Gr + 4), "f"(u1.x), "f"(u1.y), "f"(u1.z), "f"(u1.w) : "memory");
    asm volatile("red.global.add.v2.f32 [%0], {%1, %2};"
                 :: "l"(Gr + 8), "f"(u2.x), "f"(u2.y) : "memory");
}

// ============================ fused final head ==============================
// out = relu( relu( relu(agg) @ Wf1 ) @ Wf2 ). Stage 2 uses packed f32x2 FMA
// (FFMA2, 2x fp32 throughput — PTX-only pattern).

__global__ void __launch_bounds__(128) final_fused(const float* __restrict__ Wf1,
                                                   const float* __restrict__ Wf2,
                                                   float* __restrict__ out) {
    __shared__ float sW1[HIDD * FEATD];   // 2.5 KB
    __shared__ float sW2[FEATD * FEATD];  // 16 KB
    for (int i = threadIdx.x; i < HIDD * FEATD; i += blockDim.x) sW1[i] = Wf1[i];
    for (int i = threadIdx.x; i < FEATD * FEATD; i += blockDim.x) sW2[i] = Wf2[i];
    __syncthreads();

    int n = blockIdx.x * blockDim.x + threadIdx.x;
    if (n >= NN) return;

    const float4* Gr = (const float4*)(g_agg + (long)n * PADD);
    float4 g0 = Gr[0], g1 = Gr[1], g2 = Gr[2];
    float h[HIDD];
    h[0]=fmaxf(g0.x,0.f); h[1]=fmaxf(g0.y,0.f); h[2]=fmaxf(g0.z,0.f); h[3]=fmaxf(g0.w,0.f);
    h[4]=fmaxf(g1.x,0.f); h[5]=fmaxf(g1.y,0.f); h[6]=fmaxf(g1.z,0.f); h[7]=fmaxf(g1.w,0.f);
    h[8]=fmaxf(g2.x,0.f); h[9]=fmaxf(g2.y,0.f);

    // Stage 1: T = relu(h @ Wf1) -> 64 floats in regs (scalar FMA; only 640 MACs).
    const float4* sW1_4 = (const float4*)sW1;
    float4 t[16];
    #pragma unroll
    for (int c = 0; c < 16; c++) t[c] = make_float4(0.f,0.f,0.f,0.f);
    #pragma unroll
    for (int k = 0; k < HIDD; k++) {
        float hk = h[k];
        #pragma unroll
        for (int c = 0; c < 16; c++) fma4(t[c], hk, sW1_4[k * 16 + c]);
    }
    float tv[FEATD];
    #pragma unroll
    for (int c = 0; c < 16; c++) {
        tv[4*c+0] = fmaxf(t[c].x, 0.f); tv[4*c+1] = fmaxf(t[c].y, 0.f);
        tv[4*c+2] = fmaxf(t[c].z, 0.f); tv[4*c+3] = fmaxf(t[c].w, 0.f);
    }

    // Stage 2: out = relu(T @ Wf2) with packed f32x2 FMA (32 pair-accumulators).
    const unsigned long long* sW2_2 = (const unsigned long long*)sW2;
    unsigned long long acc[32];
    #pragma unroll
    for (int c = 0; c < 32; c++) acc[c] = pack2(0.f, 0.f);

    for (int g = 0; g < FEATD; g++) {
        unsigned long long xg2 = pack2(tv[g], tv[g]);
        const unsigned long long* wrow = sW2_2 + g * 32;
        #pragma unroll
        for (int c = 0; c < 32; c++) ffma2(acc[c], xg2, wrow[c]);
    }

    float4* orow = (float4*)(out + (long)n * FEATD);
    #pragma unroll
    for (int c = 0; c < 16; c++) {
        float2 p0 = unpack2(acc[2*c + 0]);
        float2 p1 = unpack2(acc[2*c + 1]);
        float4 v;
        v.x = fmaxf(p0.x, 0.f); v.y = fmaxf(p0.y, 0.f);
        v.z = fmaxf(p1.x, 0.f); v.w = fmaxf(p1.y, 0.f);
        orow[c] = v;
    }
}

// ---------------------------------------------------------------------------
// Inputs (metadata order): X, W2_0, W1_0, W2_1, W1_1, W2_2, W1_2, Wf1, Wf2,
//                          edge_src (int32), edge_dst (int32)
// ---------------------------------------------------------------------------
extern "C" void kernel_launch(void* const* d_in, const int* in_sizes, int n_in,
                              void* d_out, int out_size) {
    const float* X    = (const float*)d_in[0];
    const float* W2_0 = (const float*)d_in[1];
    const float* W1_0 = (const float*)d_in[2];
    const float* W2_1 = (const float*)d_in[3];
    const float* W1_1 = (const float*)d_in[4];
    const float* W2_2 = (const float*)d_in[5];
    const float* W1_2 = (const float*)d_in[6];
    const float* Wf1  = (const float*)d_in[7];
    const float* Wf2  = (const float*)d_in[8];
    const int*   es   = (const int*)d_in[9];
    const int*   ed   = (const int*)d_in[10];
    float* out = (float*)d_out;

    const int nodeBlocks = (NN + 127) / 128;
    const int edgeBlocks = (NE + 255) / 256;

    pre0<<<nodeBlocks, 128>>>(X, W2_0);
    edge_kernel<<<edgeBlocks, 256>>>(es, ed, W1_0);
    pre12<<<nodeBlocks, 128>>>(W2_1);
    edge_kernel<<<edgeBlocks, 256>>>(es, ed, W1_1);
    pre12<<<nodeBlocks, 128>>>(W2_2);
    edge_kernel<<<edgeBlocks, 256>>>(es, ed, W1_2);
    final_fused<<<nodeBlocks, 128>>>(Wf1, Wf2, out);
}